// round 1
// baseline (speedup 1.0000x reference)
#include <cuda_runtime.h>
#include <math.h>

#define NCLS 5
#define NQ   75
#define NN   80            // NCLS + NQ
#define FEAT 640
#define HID  4096
#define DIN  465
#define LRC  1e-3f

// ------------------------- scratch (device globals) -------------------------
__device__ float g_supp[NCLS * FEAT];
__device__ float g_query[NQ * FEAT];
__device__ float g_F[NN * FEAT];
__device__ float g_nrm[NN];
__device__ float g_sim[NN * NN];
__device__ int   g_idx[NN * 81];
__device__ float g_x[NN * DIN];
__device__ float g_h1[NN * HID];
__device__ float g_h2[NN * HID];
__device__ float g_G[NN * NN];
__device__ float g_parts[4 * NN * HID];   // max(4*80*4096, 32*80*465)

// map mask index k -> (r, c), r in 0..5, c in r+1..80, flat row-major order
__device__ __forceinline__ void mask_rc(int k, int& r, int& c) {
    int base;
    if      (k < 80)  { r = 0; base = 0;   }
    else if (k < 159) { r = 1; base = 80;  }
    else if (k < 237) { r = 2; base = 159; }
    else if (k < 314) { r = 3; base = 237; }
    else if (k < 390) { r = 4; base = 314; }
    else              { r = 5; base = 390; }
    c = r + 1 + (k - base);
}

// ------------------------- init: supp mean + query copy ---------------------
__global__ void k_init(const float* __restrict__ fs, const float* __restrict__ fq) {
    int idx = blockIdx.x * 256 + threadIdx.x;
    if (idx >= NN * FEAT) return;
    int r = idx / FEAT, d = idx % FEAT;
    if (r < NCLS) {
        float s = 0.f;
        #pragma unroll
        for (int sh = 0; sh < 5; sh++) s += fs[(r * 5 + sh) * FEAT + d];
        g_supp[r * FEAT + d] = s / 5.0f;
    } else {
        g_query[(r - NCLS) * FEAT + d] = fq[(r - NCLS) * FEAT + d];
    }
}

// ------------------------- normalize rows -> g_F, g_nrm ---------------------
__global__ void k_normalize() {
    int i = blockIdx.x;
    int tid = threadIdx.x;
    const float* src = (i < NCLS) ? (g_supp + i * FEAT) : (g_query + (i - NCLS) * FEAT);
    __shared__ float red[256];
    float s = 0.f;
    for (int d = tid; d < FEAT; d += 256) { float v = src[d]; s += v * v; }
    red[tid] = s; __syncthreads();
    for (int o = 128; o > 0; o >>= 1) { if (tid < o) red[tid] += red[tid + o]; __syncthreads(); }
    float nrm = fmaxf(sqrtf(red[0]), 1e-12f);
    if (tid == 0) g_nrm[i] = nrm;
    for (int d = tid; d < FEAT; d += 256) g_F[i * FEAT + d] = src[d] / nrm;
}

// ------------------------- sim = F F^T (row per block) ----------------------
__global__ void k_sim() {
    int i = blockIdx.x;
    int tid = threadIdx.x;
    __shared__ float Fi[FEAT];
    for (int d = tid; d < FEAT; d += 256) Fi[d] = g_F[i * FEAT + d];
    __syncthreads();
    int w = tid >> 5, l = tid & 31;
    for (int j = w; j < NN; j += 8) {
        const float* Fj = g_F + j * FEAT;
        float p = 0.f;
        for (int d = l; d < FEAT; d += 32) p += Fi[d] * Fj[d];
        #pragma unroll
        for (int o = 16; o > 0; o >>= 1) p += __shfl_xor_sync(0xffffffffu, p, o);
        if (l == 0) g_sim[i * NN + j] = p;
    }
}

// ------------- stable-descending rank sort + gather DNI inputs --------------
__global__ void k_sortgather() {
    int i = blockIdx.x;
    int tid = threadIdx.x;   // 128 threads
    __shared__ float srow[NN];
    __shared__ int a[81];
    for (int j = tid; j < NN; j += 128) srow[j] = g_sim[i * NN + j];
    if (tid == 0) a[0] = i;
    __syncthreads();
    if (tid < NCLS) {   // support: stable sort of 5
        float v = srow[tid];
        int rank = 0;
        #pragma unroll
        for (int j = 0; j < NCLS; j++) {
            float u = srow[j];
            if (j != tid && (u > v || (u == v && j < tid))) rank++;
        }
        a[1 + rank] = tid;
    }
    if (tid < NQ) {     // query: stable sort of 75
        float v = srow[NCLS + tid];
        int rank = 0;
        for (int j = 0; j < NQ; j++) {
            float u = srow[NCLS + j];
            if (u > v || (u == v && j < tid)) rank++;
        }
        a[6 + rank] = NCLS + tid;
    }
    __syncthreads();
    for (int t = tid; t < 81; t += 128) g_idx[i * 81 + t] = a[t];
    for (int k = tid; k < DIN; k += 128) {
        int r, c; mask_rc(k, r, c);
        g_x[i * DIN + k] = g_sim[a[r] * NN + a[c]];
    }
    for (int t = tid; t < NN; t += 128) g_G[i * NN + t] = 0.f;   // pre-zero for scatter
}

// ------------------------- GEMM: Cpart = A[80xK-range] * W[NxK]^T ----------
// BN=128, BK=16, 256 threads, thread tile 10m x 4n. Split-K via blockIdx.y.
__global__ void __launch_bounds__(256) k_gemm(
    const float* __restrict__ A, int K, int Kchunk,
    const float* __restrict__ W, int N,
    float* __restrict__ Cpart)
{
    __shared__ float Xs[16][80];
    __shared__ float Ws[16][132];   // pad to keep 16B-aligned float4 reads, tame STS conflicts
    int n0 = blockIdx.x * 128;
    int k0 = blockIdx.y * Kchunk;
    int k1 = min(k0 + Kchunk, K);
    int tid = threadIdx.x;
    int w = tid >> 5, l = tid & 31;

    float acc[10][4];
    #pragma unroll
    for (int r = 0; r < 10; r++)
        #pragma unroll
        for (int j = 0; j < 4; j++) acc[r][j] = 0.f;

    for (int kb = k0; kb < k1; kb += 16) {
        #pragma unroll
        for (int i = 0; i < 5; i++) {      // 16x80 A tile
            int e = tid + i * 256;
            int m = e >> 4, kk = e & 15;
            int k = kb + kk;
            Xs[kk][m] = (k < k1) ? A[m * K + k] : 0.f;
        }
        #pragma unroll
        for (int i = 0; i < 8; i++) {      // 16x128 W tile
            int e = tid + i * 256;
            int kk = e & 15, n = e >> 4;
            int gn = n0 + n;
            int k = kb + kk;
            Ws[kk][n] = (gn < N && k < k1) ? W[(size_t)gn * K + k] : 0.f;
        }
        __syncthreads();
        #pragma unroll
        for (int kk = 0; kk < 16; kk++) {
            float4 wv = *reinterpret_cast<const float4*>(&Ws[kk][l * 4]);
            #pragma unroll
            for (int r = 0; r < 10; r++) {
                float x = Xs[kk][w * 10 + r];
                acc[r][0] += x * wv.x;
                acc[r][1] += x * wv.y;
                acc[r][2] += x * wv.z;
                acc[r][3] += x * wv.w;
            }
        }
        __syncthreads();
    }
    float* Cp = Cpart + (size_t)blockIdx.y * NN * N;
    #pragma unroll
    for (int r = 0; r < 10; r++) {
        int m = w * 10 + r;
        #pragma unroll
        for (int j = 0; j < 4; j++) {
            int n = n0 + l * 4 + j;
            if (n < N) Cp[(size_t)m * N + n] = acc[r][j];
        }
    }
}

// ------------------------- combine split-K parts + bias + relu --------------
__global__ void k_combine(const float* __restrict__ parts, int S,
                          const float* __restrict__ bias, int relu,
                          float* __restrict__ H, int N) {
    int m = blockIdx.x;
    for (int n = threadIdx.x; n < N; n += blockDim.x) {
        float v = bias[n];
        for (int s = 0; s < S; s++) v += parts[((size_t)s * NN + m) * N + n];
        if (relu) v = fmaxf(v, 0.f);
        H[(size_t)m * N + n] = v;
    }
}

// --------- scatter: Gbar += g at (a_r,a_c) and (a_c,a_r)  (g = sum parts+b3)
__global__ void k_scatter(const float* __restrict__ parts, const float* __restrict__ b3) {
    int i = blockIdx.x;
    int tid = threadIdx.x;   // 128
    __shared__ int a[81];
    for (int t = tid; t < 81; t += 128) a[t] = g_idx[i * 81 + t];
    __syncthreads();
    for (int k = tid; k < DIN; k += 128) {
        float v = b3[k];
        #pragma unroll 4
        for (int s = 0; s < 32; s++) v += parts[((size_t)s * NN + i) * DIN + k];
        int r, c; mask_rc(k, r, c);
        int p = a[r], q = a[c];
        atomicAdd(&g_G[p * NN + q], v);
        atomicAdd(&g_G[q * NN + p], v);
    }
}

// --------- Fbar = Gbar F (selected rows); normalize-VJP; SGD update ---------
__global__ void k_update(int lo, float* __restrict__ target) {
    int p = lo + blockIdx.x;
    int tid = threadIdx.x;
    __shared__ float Gp[NN];
    __shared__ float fb[FEAT];
    __shared__ float red[256];
    for (int q = tid; q < NN; q += 256) Gp[q] = g_G[p * NN + q];
    __syncthreads();
    for (int d = tid; d < FEAT; d += 256) {
        float s = 0.f;
        #pragma unroll 8
        for (int q = 0; q < NN; q++) s += Gp[q] * g_F[q * FEAT + d];
        fb[d] = s;
    }
    __syncthreads();
    float part = 0.f;
    for (int d = tid; d < FEAT; d += 256) part += fb[d] * g_F[p * FEAT + d];
    red[tid] = part; __syncthreads();
    for (int o = 128; o > 0; o >>= 1) { if (tid < o) red[tid] += red[tid + o]; __syncthreads(); }
    float dot = red[0];
    float inv = 1.f / g_nrm[p];
    for (int d = tid; d < FEAT; d += 256) {
        float fp = g_F[p * FEAT + d];
        float dX = (fb[d] - dot * fp) * inv;
        target[(p - lo) * FEAT + d] -= LRC * dX;
    }
}

// ------------------------- final output: (sim_sq * scale)^T -----------------
__global__ void k_final(const float* __restrict__ scale, float* __restrict__ out) {
    int q = blockIdx.x;   // 0..74
    int tid = threadIdx.x;
    __shared__ float Fq[FEAT];
    for (int d = tid; d < FEAT; d += 256) Fq[d] = g_F[(NCLS + q) * FEAT + d];
    __syncthreads();
    int w = tid >> 5, l = tid & 31;
    if (w < NCLS) {
        float p = 0.f;
        for (int d = l; d < FEAT; d += 32) p += g_F[w * FEAT + d] * Fq[d];
        #pragma unroll
        for (int o = 16; o > 0; o >>= 1) p += __shfl_xor_sync(0xffffffffu, p, o);
        if (l == 0) out[q * NCLS + w] = p * scale[0];
    }
}

// ----------------------------------------------------------------------------
extern "C" void kernel_launch(void* const* d_in, const int* in_sizes, int n_in,
                              void* d_out, int out_size) {
    const float* fs    = (const float*)d_in[0];
    const float* fq    = (const float*)d_in[1];
    const float* scale = (const float*)d_in[2];

    float *px, *ph1, *ph2, *pp, *ps, *pq;
    cudaGetSymbolAddress((void**)&px,  g_x);
    cudaGetSymbolAddress((void**)&ph1, g_h1);
    cudaGetSymbolAddress((void**)&ph2, g_h2);
    cudaGetSymbolAddress((void**)&pp,  g_parts);
    cudaGetSymbolAddress((void**)&ps,  g_supp);
    cudaGetSymbolAddress((void**)&pq,  g_query);

    k_init<<<200, 256>>>(fs, fq);

    for (int step = 0; step < 3; step++) {
        for (int br = 0; br < 2; br++) {
            const float* W1 = (const float*)d_in[3 + 6 * br + 0];
            const float* b1 = (const float*)d_in[3 + 6 * br + 1];
            const float* W2 = (const float*)d_in[3 + 6 * br + 2];
            const float* b2 = (const float*)d_in[3 + 6 * br + 3];
            const float* W3 = (const float*)d_in[3 + 6 * br + 4];
            const float* b3 = (const float*)d_in[3 + 6 * br + 5];

            k_normalize<<<NN, 256>>>();
            k_sim<<<NN, 256>>>();
            k_sortgather<<<NN, 128>>>();

            // L1: (80x465) @ (4096x465)^T   -> h1 (relu)
            k_gemm<<<dim3(32, 4), 256>>>(px, DIN, 128, W1, HID, pp);
            k_combine<<<NN, 256>>>(pp, 4, b1, 1, ph1, HID);
            // L2: (80x4096) @ (4096x4096)^T -> h2 (relu)
            k_gemm<<<dim3(32, 4), 256>>>(ph1, HID, 1024, W2, HID, pp);
            k_combine<<<NN, 256>>>(pp, 4, b2, 1, ph2, HID);
            // L3: (80x4096) @ (465x4096)^T  -> g (bias added in scatter)
            k_gemm<<<dim3(4, 32), 256>>>(ph2, HID, 128, W3, DIN, pp);

            k_scatter<<<NN, 128>>>(pp, b3);
            if (br == 0) k_update<<<NCLS, 256>>>(0, ps);
            else         k_update<<<NQ, 256>>>(NCLS, pq);
        }
    }

    k_normalize<<<NN, 256>>>();
    k_final<<<NQ, 256>>>(scale, (float*)d_out);
}

// round 2
// speedup vs baseline: 2.8764x; 2.8764x over previous
#include <cuda_runtime.h>
#include <cuda_bf16.h>
#include <math.h>
#include <stdint.h>

#define NCLS 5
#define NQ   75
#define NN   80
#define FEAT 640
#define HID  4096
#define DIN  465
#define KPAD 512
#define LRC  1e-3f

// ------------------------- scratch (device globals) -------------------------
__device__ float g_supp[NCLS * FEAT];
__device__ float g_query[NQ * FEAT];
__device__ float g_F[NN * FEAT];
__device__ float g_nrm[NN];
__device__ float g_sim[NN * NN];
__device__ int   g_idx[NN * 81];
__device__ float g_G[NN * NN];
__device__ float g_parts[4 * NN * HID];          // split-K partials (max 1.31M floats)
__device__ __nv_bfloat16 g_xb [NN * KPAD];       // DNI input, bf16, zero-padded
__device__ __nv_bfloat16 g_h1b[NN * HID];
__device__ __nv_bfloat16 g_h2b[NN * HID];
__device__ __nv_bfloat16 g_W1b[2][HID * KPAD];   // [4096][512] (K padded)
__device__ __nv_bfloat16 g_W2b[2][HID * HID];
__device__ __nv_bfloat16 g_W3b[2][KPAD * HID];   // [512][4096] (N padded, pad rows = 0)

// map mask index k -> (r, c), r in 0..5, c in r+1..80 (flat row-major order)
__device__ __forceinline__ void mask_rc(int k, int& r, int& c) {
    int base;
    if      (k < 80)  { r = 0; base = 0;   }
    else if (k < 159) { r = 1; base = 80;  }
    else if (k < 237) { r = 2; base = 159; }
    else if (k < 314) { r = 3; base = 237; }
    else if (k < 390) { r = 4; base = 314; }
    else              { r = 5; base = 390; }
    c = r + 1 + (k - base);
}

// ------------------------- PTX helpers --------------------------------------
__device__ __forceinline__ uint32_t s_u32(const void* p) {
    return (uint32_t)__cvta_generic_to_shared(p);
}
__device__ __forceinline__ void ldsm_x4(uint32_t* r, uint32_t addr) {
    asm volatile("ldmatrix.sync.aligned.m8n8.x4.shared.b16 {%0,%1,%2,%3}, [%4];"
        : "=r"(r[0]), "=r"(r[1]), "=r"(r[2]), "=r"(r[3]) : "r"(addr));
}
__device__ __forceinline__ void ldsm_x2(uint32_t* r, uint32_t addr) {
    asm volatile("ldmatrix.sync.aligned.m8n8.x2.shared.b16 {%0,%1}, [%2];"
        : "=r"(r[0]), "=r"(r[1]) : "r"(addr));
}
__device__ __forceinline__ void mma_bf16(float* d, const uint32_t* a, const uint32_t* b) {
    asm volatile("mma.sync.aligned.m16n8k16.row.col.f32.bf16.bf16.f32 "
        "{%0,%1,%2,%3}, {%4,%5,%6,%7}, {%8,%9}, {%0,%1,%2,%3};"
        : "+f"(d[0]), "+f"(d[1]), "+f"(d[2]), "+f"(d[3])
        : "r"(a[0]), "r"(a[1]), "r"(a[2]), "r"(a[3]), "r"(b[0]), "r"(b[1]));
}
__device__ __forceinline__ void cp16(void* s, const void* g) {
    asm volatile("cp.async.cg.shared.global [%0], [%1], 16;" :: "r"(s_u32(s)), "l"(g));
}
#define CP_COMMIT asm volatile("cp.async.commit_group;")
#define CP_WAIT0  asm volatile("cp.async.wait_group 0;")

// ------------------------- init: supp mean + query copy ---------------------
__global__ void k_init(const float* __restrict__ fs, const float* __restrict__ fq) {
    int idx = blockIdx.x * 256 + threadIdx.x;
    if (idx >= NN * FEAT) return;
    int r = idx / FEAT, d = idx % FEAT;
    if (r < NCLS) {
        float s = 0.f;
        #pragma unroll
        for (int sh = 0; sh < 5; sh++) s += fs[(r * 5 + sh) * FEAT + d];
        g_supp[r * FEAT + d] = s / 5.0f;
    } else {
        g_query[(r - NCLS) * FEAT + d] = fq[(r - NCLS) * FEAT + d];
    }
}

// ------------------------- convert weights fp32 -> padded bf16 --------------
__global__ void k_conv(const float* __restrict__ src, __nv_bfloat16* __restrict__ dst,
                       int rows, int cols, int dstStride, int total) {
    int idx = blockIdx.x * 256 + threadIdx.x;
    if (idx >= total) return;
    int r = idx / dstStride, c = idx - r * dstStride;
    float v = (r < rows && c < cols) ? src[(size_t)r * cols + c] : 0.f;
    dst[idx] = __float2bfloat16(v);
}

// ------------------------- normalize rows -> g_F, g_nrm ---------------------
__global__ void k_normalize() {
    int i = blockIdx.x;
    int tid = threadIdx.x;
    const float* src = (i < NCLS) ? (g_supp + i * FEAT) : (g_query + (i - NCLS) * FEAT);
    __shared__ float red[256];
    float s = 0.f;
    for (int d = tid; d < FEAT; d += 256) { float v = src[d]; s += v * v; }
    red[tid] = s; __syncthreads();
    for (int o = 128; o > 0; o >>= 1) { if (tid < o) red[tid] += red[tid + o]; __syncthreads(); }
    float nrm = fmaxf(sqrtf(red[0]), 1e-12f);
    if (tid == 0) g_nrm[i] = nrm;
    for (int d = tid; d < FEAT; d += 256) g_F[i * FEAT + d] = src[d] / nrm;
}

// ------------------------- sim = F F^T (row per block) ----------------------
__global__ void k_sim() {
    int i = blockIdx.x;
    int tid = threadIdx.x;
    __shared__ float Fi[FEAT];
    for (int d = tid; d < FEAT; d += 256) Fi[d] = g_F[i * FEAT + d];
    __syncthreads();
    int w = tid >> 5, l = tid & 31;
    for (int j = w; j < NN; j += 8) {
        const float* Fj = g_F + j * FEAT;
        float p = 0.f;
        for (int d = l; d < FEAT; d += 32) p += Fi[d] * Fj[d];
        #pragma unroll
        for (int o = 16; o > 0; o >>= 1) p += __shfl_xor_sync(0xffffffffu, p, o);
        if (l == 0) g_sim[i * NN + j] = p;
    }
}

// ------------- stable-descending rank sort + gather DNI inputs (bf16) -------
__global__ void k_sortgather() {
    int i = blockIdx.x;
    int tid = threadIdx.x;   // 128 threads
    __shared__ float srow[NN];
    __shared__ int a[81];
    for (int j = tid; j < NN; j += 128) srow[j] = g_sim[i * NN + j];
    if (tid == 0) a[0] = i;
    __syncthreads();
    if (tid < NCLS) {
        float v = srow[tid];
        int rank = 0;
        #pragma unroll
        for (int j = 0; j < NCLS; j++) {
            float u = srow[j];
            if (j != tid && (u > v || (u == v && j < tid))) rank++;
        }
        a[1 + rank] = tid;
    }
    if (tid < NQ) {
        float v = srow[NCLS + tid];
        int rank = 0;
        for (int j = 0; j < NQ; j++) {
            float u = srow[NCLS + j];
            if (u > v || (u == v && j < tid)) rank++;
        }
        a[6 + rank] = NCLS + tid;
    }
    __syncthreads();
    for (int t = tid; t < 81; t += 128) g_idx[i * 81 + t] = a[t];
    for (int k = tid; k < KPAD; k += 128) {
        float v = 0.f;
        if (k < DIN) {
            int r, c; mask_rc(k, r, c);
            v = g_sim[a[r] * NN + a[c]];
        }
        g_xb[i * KPAD + k] = __float2bfloat16(v);
    }
    for (int t = tid; t < NN; t += 128) g_G[i * NN + t] = 0.f;   // pre-zero scatter target
}

// ------------------------- bf16 HMMA GEMM -----------------------------------
// Cpart[sk][80][N] = A[80 x Kchunk-slice] * W[N x K]^T, bf16 in, fp32 out.
// BM=80 (full), BN=128, BK=32. 256 threads = 8 warps; warp w -> n-tiles 2w,2w+1, all 5 m16.
#define BK 32
#define ASTR 40
#define WSTR 40
__global__ void __launch_bounds__(256) k_gemm(
    const __nv_bfloat16* __restrict__ A, int lda,
    const __nv_bfloat16* __restrict__ W, int ldw,
    int Kchunk, int N, float* __restrict__ Cpart)
{
    __shared__ __nv_bfloat16 As[2][80 * ASTR];
    __shared__ __nv_bfloat16 Ws[2][128 * WSTR];
    const int n0 = blockIdx.x * 128;
    const int k0 = blockIdx.y * Kchunk;
    const int tid = threadIdx.x, w = tid >> 5, l = tid & 31;
    const int nIter = Kchunk / BK;

    float acc[5][2][4];
    #pragma unroll
    for (int mt = 0; mt < 5; mt++)
        #pragma unroll
        for (int j = 0; j < 2; j++)
            #pragma unroll
            for (int q = 0; q < 4; q++) acc[mt][j][q] = 0.f;

    // ldmatrix per-lane row selectors
    const int arow = (l & 7) + 8 * ((l >> 3) & 1);
    const int acol = 8 * (l >> 4);
    const int brow = (l & 7);
    const int bcol = 8 * ((l >> 3) & 1);

    // prologue stage into buf 0
    {
        #pragma unroll
        for (int ch = tid; ch < 320; ch += 256) {
            int m = ch >> 2, c = ch & 3;
            cp16(&As[0][m * ASTR + c * 8], A + (size_t)m * lda + k0 + c * 8);
        }
        #pragma unroll
        for (int ch = tid; ch < 512; ch += 256) {
            int n = ch >> 2, c = ch & 3;
            cp16(&Ws[0][n * WSTR + c * 8], W + (size_t)(n0 + n) * ldw + k0 + c * 8);
        }
        CP_COMMIT;
    }

    int buf = 0;
    for (int it = 0; it < nIter; it++) {
        CP_WAIT0;
        __syncthreads();
        if (it + 1 < nIter) {
            int kb = k0 + (it + 1) * BK;
            int nb = buf ^ 1;
            #pragma unroll
            for (int ch = tid; ch < 320; ch += 256) {
                int m = ch >> 2, c = ch & 3;
                cp16(&As[nb][m * ASTR + c * 8], A + (size_t)m * lda + kb + c * 8);
            }
            #pragma unroll
            for (int ch = tid; ch < 512; ch += 256) {
                int n = ch >> 2, c = ch & 3;
                cp16(&Ws[nb][n * WSTR + c * 8], W + (size_t)(n0 + n) * ldw + kb + c * 8);
            }
            CP_COMMIT;
        }
        #pragma unroll
        for (int ks = 0; ks < 2; ks++) {
            int kk = ks * 16;
            uint32_t b[2][2];
            #pragma unroll
            for (int j = 0; j < 2; j++) {
                int nt = w * 2 + j;
                ldsm_x2(b[j], s_u32(&Ws[buf][(nt * 8 + brow) * WSTR + kk + bcol]));
            }
            #pragma unroll
            for (int mt = 0; mt < 5; mt++) {
                uint32_t a[4];
                ldsm_x4(a, s_u32(&As[buf][(mt * 16 + arow) * ASTR + kk + acol]));
                mma_bf16(acc[mt][0], a, b[0]);
                mma_bf16(acc[mt][1], a, b[1]);
            }
        }
        buf ^= 1;
    }

    float* Cp = Cpart + (size_t)blockIdx.y * NN * N;
    #pragma unroll
    for (int mt = 0; mt < 5; mt++) {
        #pragma unroll
        for (int j = 0; j < 2; j++) {
            int n = n0 + (w * 2 + j) * 8 + 2 * (l & 3);
            int m = mt * 16 + (l >> 2);
            float2 v0 = make_float2(acc[mt][j][0], acc[mt][j][1]);
            float2 v1 = make_float2(acc[mt][j][2], acc[mt][j][3]);
            *(float2*)&Cp[(size_t)m * N + n] = v0;
            *(float2*)&Cp[(size_t)(m + 8) * N + n] = v1;
        }
    }
}

// ---------------- combine split-K (S=4) + bias + relu -> bf16 ---------------
__global__ void k_combine(const float* __restrict__ parts, const float* __restrict__ bias,
                          __nv_bfloat16* __restrict__ Hb, int N) {
    int m = blockIdx.x;
    for (int n = threadIdx.x; n < N; n += blockDim.x) {
        float v = bias[n];
        #pragma unroll
        for (int s = 0; s < 4; s++) v += parts[((size_t)s * NN + m) * N + n];
        v = fmaxf(v, 0.f);
        Hb[(size_t)m * N + n] = __float2bfloat16(v);
    }
}

// -------- scatter: Gbar += g at (a_r,a_c) and (a_c,a_r)  (g = sum16 + b3) ----
__global__ void k_scatter(const float* __restrict__ parts, const float* __restrict__ b3) {
    int i = blockIdx.x;
    int tid = threadIdx.x;   // 128
    __shared__ int a[81];
    for (int t = tid; t < 81; t += 128) a[t] = g_idx[i * 81 + t];
    __syncthreads();
    for (int k = tid; k < DIN; k += 128) {
        float v = b3[k];
        #pragma unroll
        for (int s = 0; s < 16; s++) v += parts[((size_t)s * NN + i) * KPAD + k];
        int r, c; mask_rc(k, r, c);
        atomicAdd(&g_G[a[r] * NN + a[c]], v);
        atomicAdd(&g_G[a[c] * NN + a[r]], v);
    }
}

// --------- Fbar = Gbar F (selected rows); normalize-VJP; SGD update ---------
__global__ void k_update(int lo, float* __restrict__ target) {
    int p = lo + blockIdx.x;
    int tid = threadIdx.x;
    __shared__ float Gp[NN];
    __shared__ float fb[FEAT];
    __shared__ float red[256];
    for (int q = tid; q < NN; q += 256) Gp[q] = g_G[p * NN + q];
    __syncthreads();
    for (int d = tid; d < FEAT; d += 256) {
        float s = 0.f;
        #pragma unroll 8
        for (int q = 0; q < NN; q++) s += Gp[q] * g_F[q * FEAT + d];
        fb[d] = s;
    }
    __syncthreads();
    float part = 0.f;
    for (int d = tid; d < FEAT; d += 256) part += fb[d] * g_F[p * FEAT + d];
    red[tid] = part; __syncthreads();
    for (int o = 128; o > 0; o >>= 1) { if (tid < o) red[tid] += red[tid + o]; __syncthreads(); }
    float dot = red[0];
    float inv = 1.f / g_nrm[p];
    for (int d = tid; d < FEAT; d += 256) {
        float fp = g_F[p * FEAT + d];
        float dX = (fb[d] - dot * fp) * inv;
        target[(p - lo) * FEAT + d] -= LRC * dX;
    }
}

// ------------------------- final output: (sim_sq * scale)^T -----------------
__global__ void k_final(const float* __restrict__ scale, float* __restrict__ out) {
    int q = blockIdx.x;
    int tid = threadIdx.x;
    __shared__ float Fq[FEAT];
    for (int d = tid; d < FEAT; d += 256) Fq[d] = g_F[(NCLS + q) * FEAT + d];
    __syncthreads();
    int w = tid >> 5, l = tid & 31;
    if (w < NCLS) {
        float p = 0.f;
        for (int d = l; d < FEAT; d += 32) p += g_F[w * FEAT + d] * Fq[d];
        #pragma unroll
        for (int o = 16; o > 0; o >>= 1) p += __shfl_xor_sync(0xffffffffu, p, o);
        if (l == 0) out[q * NCLS + w] = p * scale[0];
    }
}

// ----------------------------------------------------------------------------
extern "C" void kernel_launch(void* const* d_in, const int* in_sizes, int n_in,
                              void* d_out, int out_size) {
    const float* fs    = (const float*)d_in[0];
    const float* fq    = (const float*)d_in[1];
    const float* scale = (const float*)d_in[2];

    float *pp, *ps, *pq;
    __nv_bfloat16 *pxb, *ph1b, *ph2b, *pw1b, *pw2b, *pw3b;
    cudaGetSymbolAddress((void**)&pp,   g_parts);
    cudaGetSymbolAddress((void**)&ps,   g_supp);
    cudaGetSymbolAddress((void**)&pq,   g_query);
    cudaGetSymbolAddress((void**)&pxb,  g_xb);
    cudaGetSymbolAddress((void**)&ph1b, g_h1b);
    cudaGetSymbolAddress((void**)&ph2b, g_h2b);
    cudaGetSymbolAddress((void**)&pw1b, g_W1b);
    cudaGetSymbolAddress((void**)&pw2b, g_W2b);
    cudaGetSymbolAddress((void**)&pw3b, g_W3b);

    k_init<<<200, 256>>>(fs, fq);

    // convert weights to padded bf16 (once per launch; weights constant)
    for (int br = 0; br < 2; br++) {
        const float* W1 = (const float*)d_in[3 + 6 * br + 0];
        const float* W2 = (const float*)d_in[3 + 6 * br + 2];
        const float* W3 = (const float*)d_in[3 + 6 * br + 4];
        int t1 = HID * KPAD, t2 = HID * HID, t3 = KPAD * HID;
        k_conv<<<(t1 + 255) / 256, 256>>>(W1, pw1b + (size_t)br * t1, HID, DIN, KPAD, t1);
        k_conv<<<(t2 + 255) / 256, 256>>>(W2, pw2b + (size_t)br * t2, HID, HID, HID, t2);
        k_conv<<<(t3 + 255) / 256, 256>>>(W3, pw3b + (size_t)br * t3, DIN, HID, HID, t3);
    }

    for (int step = 0; step < 3; step++) {
        for (int br = 0; br < 2; br++) {
            const float* b1 = (const float*)d_in[3 + 6 * br + 1];
            const float* b2 = (const float*)d_in[3 + 6 * br + 3];
            const float* b3 = (const float*)d_in[3 + 6 * br + 5];
            __nv_bfloat16* W1b = pw1b + (size_t)br * (HID * KPAD);
            __nv_bfloat16* W2b = pw2b + (size_t)br * (HID * HID);
            __nv_bfloat16* W3b = pw3b + (size_t)br * (KPAD * HID);

            k_normalize<<<NN, 256>>>();
            k_sim<<<NN, 256>>>();
            k_sortgather<<<NN, 128>>>();

            // L1: (80x512) @ (4096x512)^T, splitK=4 (Kchunk 128)
            k_gemm<<<dim3(32, 4), 256>>>(pxb, KPAD, W1b, KPAD, 128, HID, pp);
            k_combine<<<NN, 256>>>(pp, b1, ph1b, HID);
            // L2: (80x4096) @ (4096x4096)^T, splitK=4 (Kchunk 1024)
            k_gemm<<<dim3(32, 4), 256>>>(ph1b, HID, W2b, HID, 1024, HID, pp);
            k_combine<<<NN, 256>>>(pp, b2, ph2b, HID);
            // L3: (80x4096) @ (512x4096)^T, splitK=16 (Kchunk 256), N=512
            k_gemm<<<dim3(4, 16), 256>>>(ph2b, HID, W3b, HID, 256, KPAD, pp);

            k_scatter<<<NN, 128>>>(pp, b3);
            if (br == 0) k_update<<<NCLS, 256>>>(0, ps);
            else         k_update<<<NQ, 256>>>(NCLS, pq);
        }
    }

    k_normalize<<<NN, 256>>>();
    k_final<<<NQ, 256>>>(scale, (float*)d_out);
}